// round 8
// baseline (speedup 1.0000x reference)
#include <cuda_runtime.h>

#define N_NODES 2000
#define N_EDGES 16000
#define BB 4
#define L1D 12
#define IN_DIM 16
#define REF 32
#define HID 32
#define OUTD 16
#define NB (N_NODES*BB)   // 8000
#define MAXDEG 96

typedef unsigned long long u64;
typedef unsigned int u32;

// ---------------- scratch (device globals; no allocation) ----------------
__device__ float g_state[NB*L1D*HID];   // [n][b][l][h]
__device__ float g_A[NB*2048];          // A[nb][c], c=k*32+h, k=0..63 (b_metaW folded in)
__device__ float g_Bm[NB*2048];         // Bm[nb][c]
__device__ float g_P1[NB*L1D*HID];      // state @ A1
__device__ float g_P4[NB*L1D*HID];      // state @ B2
__device__ float g_mbs[NB*HID];
__device__ float g_mbd[NB*HID];
__device__ int   g_counts[N_NODES];     // zero at load; k_scan re-zeroes each replay
__device__ int   g_cursor[N_NODES];
__device__ int   g_offsets[N_NODES+1];
__device__ int   g_sorted[N_EDGES];

// ---------------- f32x2 packed helpers (Blackwell) ----------------
__device__ __forceinline__ u64 pk2(float lo, float hi) {
    u64 r; asm("mov.b64 %0, {%1,%2};" : "=l"(r) : "f"(lo), "f"(hi)); return r;
}
__device__ __forceinline__ u64 pk2s(float v) { return pk2(v, v); }
__device__ __forceinline__ void upk2(float& lo, float& hi, u64 v) {
    asm("mov.b64 {%0,%1}, %2;" : "=f"(lo), "=f"(hi) : "l"(v));
}
__device__ __forceinline__ u64 fma2(u64 a, u64 b, u64 c) {
    u64 d; asm("fma.rn.f32x2 %0, %1, %2, %3;" : "=l"(d) : "l"(a), "l"(b), "l"(c)); return d;
}
__device__ __forceinline__ u64 add2(u64 a, u64 b) {
    u64 d; asm("add.rn.f32x2 %0, %1, %2;" : "=l"(d) : "l"(a), "l"(b)); return d;
}

// ---------------- cp.async helpers ----------------
__device__ __forceinline__ void cpa16(u32 s, const void* g) {
    asm volatile("cp.async.cg.shared.global [%0], [%1], 16;" :: "r"(s), "l"(g));
}
__device__ __forceinline__ void cpcommit() {
    asm volatile("cp.async.commit_group;");
}
template<int N> __device__ __forceinline__ void cpwait() {
    asm volatile("cp.async.wait_group %0;" :: "n"(N));
}

// ---------------- L1: fused state(+hist) | meta hypernetwork GEMM ----------------
// grid 6000 x 256 threads:
//   blocks [0,2000): state for node bx + histogram for edges [8*bx, 8*bx+8)
//   blocks [2000,6000): meta tile m = bx-2000: nb0 = (m%250)*32, c0 = (m/250)*128
__global__ void __launch_bounds__(256) k_statehist_meta(
        const float* __restrict__ x, const float* __restrict__ W_in,
        const float* __restrict__ b_in, const int* __restrict__ dst,
        const float* __restrict__ mk, const float* __restrict__ W,
        const float* __restrict__ bW) {
    __shared__ __align__(16) float shm[9216];   // max(state 1312, meta 9216) floats
    int t = threadIdx.x;
    int bx = blockIdx.x;

    if (bx < N_NODES) {
        // ---- state + hist ----
        int n = bx;
        float* xs = shm;            // 768
        float* ws = shm + 768;      // 512
        float* bs = shm + 1280;     // 32
        if (t < 8) atomicAdd(&g_counts[dst[8*n + t]], 1);
        for (int i = t; i < IN_DIM*HID; i += 256) ws[i] = W_in[i];
        if (t < HID) bs[t] = b_in[t];
        for (int i = t; i < BB*L1D*IN_DIM; i += 256) {
            int bl = i / IN_DIM, ii = i % IN_DIM;
            int b = bl / L1D, l = bl % L1D;
            xs[i] = x[((b*L1D + l)*N_NODES + n)*IN_DIM + ii];
        }
        __syncthreads();
        for (int o = t; o < BB*L1D*HID; o += 256) {
            int h = o % HID, bl = o / HID;
            float acc = bs[h];
            #pragma unroll
            for (int i = 0; i < IN_DIM; i++)
                acc = fmaf(xs[bl*IN_DIM + i], ws[i*HID + h], acc);
            g_state[n*(BB*L1D*HID) + o] = acc;
        }
        return;
    }

    // ---- meta GEMM tile ----
    int m = bx - N_NODES;
    int nb0 = (m % 250) * 32;
    int c0  = (m / 250) * 128;
    float* mks = shm;           // 32x32 = 1024
    float* wA  = shm + 1024;    // 32x128 = 4096
    float* wB  = shm + 5120;    // 4096
    for (int i = t; i < 1024; i += 256) {
        int row = i >> 5, r = i & 31;
        int nb = nb0 + row, n = nb >> 2, b = nb & 3;
        mks[i] = mk[(b*N_NODES + n)*REF + r];
    }
    for (int i = t; i < 1024; i += 256) {
        int r = (i*4) >> 7, c = (i*4) & 127;
        *(float4*)&wA[r*128 + c] = *(const float4*)&W[r*2048 + c0 + c];
        *(float4*)&wB[r*128 + c] = *(const float4*)&W[(r + REF)*2048 + c0 + c];
    }
    __syncthreads();
    int tc = t & 15, tr = t >> 4;     // 16 col-groups x 16 row-groups
    int row0 = tr * 2, col0 = tc * 8;
    u64 accA[2][4], accB[2][4];
    #pragma unroll
    for (int i = 0; i < 2; i++)
        #pragma unroll
        for (int j = 0; j < 4; j++) { accA[i][j] = 0ull; accB[i][j] = 0ull; }
    #pragma unroll 8
    for (int r = 0; r < REF; r++) {
        ulonglong2 wa0 = *(const ulonglong2*)&wA[r*128 + col0];
        ulonglong2 wa1 = *(const ulonglong2*)&wA[r*128 + col0 + 4];
        ulonglong2 wb0 = *(const ulonglong2*)&wB[r*128 + col0];
        ulonglong2 wb1 = *(const ulonglong2*)&wB[r*128 + col0 + 4];
        #pragma unroll
        for (int i = 0; i < 2; i++) {
            u64 a = pk2s(mks[(row0 + i)*32 + r]);
            accA[i][0] = fma2(a, wa0.x, accA[i][0]);
            accA[i][1] = fma2(a, wa0.y, accA[i][1]);
            accA[i][2] = fma2(a, wa1.x, accA[i][2]);
            accA[i][3] = fma2(a, wa1.y, accA[i][3]);
            accB[i][0] = fma2(a, wb0.x, accB[i][0]);
            accB[i][1] = fma2(a, wb0.y, accB[i][1]);
            accB[i][2] = fma2(a, wb1.x, accB[i][2]);
            accB[i][3] = fma2(a, wb1.y, accB[i][3]);
        }
    }
    ulonglong2 bv0 = *(const ulonglong2*)&bW[c0 + col0];
    ulonglong2 bv1 = *(const ulonglong2*)&bW[c0 + col0 + 4];
    #pragma unroll
    for (int i = 0; i < 2; i++) {
        int nb = nb0 + row0 + i;
        ulonglong2 oa0, oa1, ob0, ob1;
        oa0.x = add2(accA[i][0], bv0.x); oa0.y = add2(accA[i][1], bv0.y);
        oa1.x = add2(accA[i][2], bv1.x); oa1.y = add2(accA[i][3], bv1.y);
        ob0.x = accB[i][0]; ob0.y = accB[i][1];
        ob1.x = accB[i][2]; ob1.y = accB[i][3];
        *(ulonglong2*)&g_A[nb*2048 + c0 + col0]      = oa0;
        *(ulonglong2*)&g_A[nb*2048 + c0 + col0 + 4]  = oa1;
        *(ulonglong2*)&g_Bm[nb*2048 + c0 + col0]     = ob0;
        *(ulonglong2*)&g_Bm[nb*2048 + c0 + col0 + 4] = ob1;
    }
}

// ---------------- L2: scan (also re-zeroes g_counts for next replay) ----------------
__global__ void k_scan() {
    __shared__ int sb[1024];
    int t = threadIdx.x;
    int i0 = 2*t, i1 = 2*t + 1;
    int a0 = (i0 < N_NODES) ? g_counts[i0] : 0;
    int a1 = (i1 < N_NODES) ? g_counts[i1] : 0;
    sb[t] = a0 + a1;
    __syncthreads();
    for (int off = 1; off < 1024; off <<= 1) {
        int v = (t >= off) ? sb[t - off] : 0;
        __syncthreads();
        sb[t] += v;
        __syncthreads();
    }
    int excl = sb[t] - (a0 + a1);
    if (i0 < N_NODES) { g_offsets[i0] = excl;      g_cursor[i0] = excl;      g_counts[i0] = 0; }
    if (i1 < N_NODES) { g_offsets[i1] = excl + a0; g_cursor[i1] = excl + a0; g_counts[i1] = 0; }
    if (t == 1023) g_offsets[N_NODES] = sb[1023];
}

// ---------------- L3: fused pmb + scatter ----------------
// grid 8000 x 128: block nb does pmb(nb); blocks < 63 also scatter 256 edges.
__global__ void __launch_bounds__(128) k_pmbscatter(
        const int* __restrict__ dst,
        const float* __restrict__ mk, const float* __restrict__ Wmb,
        const float* __restrict__ bmb) {
    int nb = blockIdx.x, n = nb >> 2, b = nb & 3;
    int t = threadIdx.x;  // 128

    if (nb < 63) {
        int e0 = nb * 256;
        for (int e = e0 + t; e < e0 + 256 && e < N_EDGES; e += 128) {
            int d = dst[e];
            int pos = atomicAdd(&g_cursor[d], 1);
            g_sorted[pos] = e;   // arbitrary bin order; k_main rank-sorts
        }
    }

    __shared__ float st[L1D*HID];
    __shared__ float A1[1024];
    __shared__ float B2[1024];
    __shared__ float mks[REF];
    {
        const float4* ps = reinterpret_cast<const float4*>(&g_state[nb*L1D*HID]);
        float4* ss = reinterpret_cast<float4*>(st);
        for (int i = t; i < (L1D*HID)/4; i += 128) ss[i] = ps[i];
        const float4* pa = reinterpret_cast<const float4*>(&g_A[nb*2048]);
        const float4* pb = reinterpret_cast<const float4*>(&g_Bm[nb*2048 + 1024]);
        float4* sa = reinterpret_cast<float4*>(A1);
        float4* sb = reinterpret_cast<float4*>(B2);
        for (int i = t; i < 256; i += 128) { sa[i] = pa[i]; sb[i] = pb[i]; }
    }
    if (t < REF) mks[t] = mk[(b*N_NODES + n)*REF + t];
    __syncthreads();
    int h = t & 31, l0 = t >> 5;
    #pragma unroll
    for (int j = 0; j < 3; j++) {
        int l = l0 + 4*j;
        float p1 = 0.f, p4 = 0.f;
        #pragma unroll
        for (int k = 0; k < HID; k++) {
            float s = st[l*HID + k];
            p1 = fmaf(s, A1[k*32 + h], p1);
            p4 = fmaf(s, B2[k*32 + h], p4);
        }
        g_P1[nb*(L1D*HID) + l*32 + h] = p1;
        g_P4[nb*(L1D*HID) + l*32 + h] = p4;
    }
    if (t < HID) {
        float s1 = 0.f, s2 = bmb[t];
        #pragma unroll
        for (int r = 0; r < REF; r++) {
            s1 = fmaf(mks[r], Wmb[r*HID + t], s1);
            s2 = fmaf(mks[r], Wmb[(r + REF)*HID + t], s2);
        }
        g_mbs[nb*HID + t] = s1;
        g_mbd[nb*HID + t] = s2;
    }
}

// ---------------- L4: k_main — block = node n; warp = batch b; warp owns whole bin ----------------
#define PWW 4368
#define SMEM_MAIN ((192 + 4*PWW)*4)   // 70656 bytes -> 3 blocks/SM

__global__ void __launch_bounds__(128, 3) k_main(const int* __restrict__ src,
                                                 const float* __restrict__ W_out,
                                                 const float* __restrict__ b_out,
                                                 float* __restrict__ out) {
    extern __shared__ __align__(16) float sh[];
    int* ekeys = (int*)sh;
    int* slist = (int*)sh + 96;

    int t = threadIdx.x, wid = t >> 5, lane = t & 31;
    int n = blockIdx.x, b = wid;
    int nbd = n*4 + b;
    int es = g_offsets[n];
    int deg = g_offsets[n+1] - es;
    int degc = (deg < MAXDEG) ? deg : MAXDEG;

    if (t < degc) ekeys[t] = g_sorted[es + t];

    float* W   = sh + 192 + wid*PWW;
    float* B1d  = W;            // 1024
    float* A2b  = W + 1024;     // 2 x 1024
    float* stsS = W + 3072;     // 2 x 432
    float* stds = W + 3936;     // 432

    for (int i = lane; i < 256; i += 32)
        ((float4*)B1d)[i] = ((const float4*)&g_Bm[(size_t)nbd*2048])[i];
    for (int i = lane; i < 96; i += 32) {
        int l = i >> 3, c4 = (i & 7) * 4;
        *(float4*)&stds[l*36 + c4] = ((const float4*)&g_state[nbd*384])[i];
    }
    __syncthreads();

    if (t < degc) {
        int key = ekeys[t], r = 0;
        for (int j = 0; j < degc; j++) r += (ekeys[j] < key);
        slist[r] = src[key];
    }
    __syncthreads();

    int lg = lane >> 3, hg = lane & 7, h4 = hg * 4;
    int l0 = lg * 3;

    float4 p4m[3];
    {
        float4 md = *(const float4*)&g_mbd[nbd*32 + h4];
        #pragma unroll
        for (int j = 0; j < 3; j++) {
            float4 a = *(const float4*)&g_P4[nbd*384 + (l0 + j)*32 + h4];
            p4m[j].x = a.x + md.x; p4m[j].y = a.y + md.y;
            p4m[j].z = a.z + md.z; p4m[j].w = a.w + md.w;
        }
    }

    u32 sA2 = (u32)__cvta_generic_to_shared(A2b);
    u32 sSt = (u32)__cvta_generic_to_shared(stsS);

    u64 num[3][2], den[3][2];
    #pragma unroll
    for (int j = 0; j < 3; j++) { num[j][0]=num[j][1]=den[j][0]=den[j][1]=0ull; }

    float4 p1c[3], mbc;

    auto computeEdge = [&](int v) {
        float* A2v = A2b + v*1024;
        float* stv = stsS + v*432;
        u64 att[3][2];
        #pragma unroll
        for (int j = 0; j < 3; j++) {
            att[j][0] = pk2(p1c[j].x + p4m[j].x + mbc.x, p1c[j].y + p4m[j].y + mbc.y);
            att[j][1] = pk2(p1c[j].z + p4m[j].z + mbc.z, p1c[j].w + p4m[j].w + mbc.w);
        }
        #pragma unroll
        for (int k4 = 0; k4 < 32; k4 += 4) {
            float4 ssv[3], ddv[3];
            #pragma unroll
            for (int j = 0; j < 3; j++) {
                int l = l0 + j;
                ssv[j] = *(float4*)&stv[l*36 + k4];
                ddv[j] = *(float4*)&stds[l*36 + k4];
            }
            #pragma unroll
            for (int kk = 0; kk < 4; kk++) {
                int k = k4 + kk;
                ulonglong2 bb = *(const ulonglong2*)&B1d[k*32 + h4];
                ulonglong2 aa = *(const ulonglong2*)&A2v[k*32 + h4];
                #pragma unroll
                for (int j = 0; j < 3; j++) {
                    float sf = (kk == 0) ? ssv[j].x : (kk == 1) ? ssv[j].y
                             : (kk == 2) ? ssv[j].z : ssv[j].w;
                    float df = (kk == 0) ? ddv[j].x : (kk == 1) ? ddv[j].y
                             : (kk == 2) ? ddv[j].z : ddv[j].w;
                    u64 ss = pk2s(sf), dd = pk2s(df);
                    att[j][0] = fma2(ss, bb.x, att[j][0]);
                    att[j][1] = fma2(ss, bb.y, att[j][1]);
                    att[j][0] = fma2(dd, aa.x, att[j][0]);
                    att[j][1] = fma2(dd, aa.y, att[j][1]);
                }
            }
        }
        #pragma unroll
        for (int j = 0; j < 3; j++) {
            int l = l0 + j;
            float a0,a1,a2,a3;
            upk2(a0, a1, att[j][0]); upk2(a2, a3, att[j][1]);
            float e0 = __expf(a0), e1 = __expf(a1), e2 = __expf(a2), e3 = __expf(a3);
            u64 ep0 = pk2(e0, e1), ep1 = pk2(e2, e3);
            den[j][0] = add2(den[j][0], ep0);
            den[j][1] = add2(den[j][1], ep1);
            float4 sv = *(float4*)&stv[l*36 + h4];
            num[j][0] = fma2(ep0, pk2(sv.x, sv.y), num[j][0]);
            num[j][1] = fma2(ep1, pk2(sv.z, sv.w), num[j][1]);
        }
    };

    for (int m = 0; m < degc + 1; m++) {
        if (m < degc) {
            int nbs = slist[m]*4 + b;
            int v = m & 1;
            const float* pa = &g_A[(size_t)nbs*2048 + 1024];
            #pragma unroll
            for (int r = 0; r < 8; r++) {
                int c = lane + 32*r;
                cpa16(sA2 + v*4096 + c*16, pa + c*4);
            }
            const float* ps = &g_state[nbs*384];
            #pragma unroll
            for (int r = 0; r < 3; r++) {
                int c = lane + 32*r;
                int l = c >> 3, c4 = (c & 7) * 4;
                cpa16(sSt + v*1728 + (l*36 + c4)*4, ps + c*4);
            }
            cpcommit();
        }
        if (m > 0) {
            if (m < degc) cpwait<1>(); else cpwait<0>();
            __syncwarp();
            computeEdge((m - 1) & 1);
            __syncwarp();
        }
        if (m < degc) {
            int nbs = slist[m]*4 + b;
            #pragma unroll
            for (int j = 0; j < 3; j++)
                p1c[j] = __ldg((const float4*)&g_P1[nbs*384 + (l0 + j)*32 + h4]);
            mbc = __ldg((const float4*)&g_mbs[nbs*32 + h4]);
        }
    }

    // overflow fallback (deg > MAXDEG): synchronous, correct, rare
    for (int i = MAXDEG; i < deg; i++) {
        int nbs = src[g_sorted[es + i]]*4 + b;
        for (int c = lane; c < 256; c += 32)
            ((float4*)A2b)[c] = ((const float4*)&g_A[(size_t)nbs*2048 + 1024])[c];
        for (int c = lane; c < 96; c += 32) {
            int l = c >> 3, c4 = (c & 7) * 4;
            *(float4*)&stsS[l*36 + c4] = ((const float4*)&g_state[nbs*384])[c];
        }
        #pragma unroll
        for (int j = 0; j < 3; j++)
            p1c[j] = __ldg((const float4*)&g_P1[nbs*384 + (l0 + j)*32 + h4]);
        mbc = __ldg((const float4*)&g_mbs[nbs*32 + h4]);
        __syncwarp();
        computeEdge(0);
        __syncwarp();
    }

    float* news = A2b;
    __syncwarp();
    #pragma unroll
    for (int j = 0; j < 3; j++) {
        int l = l0 + j;
        float n0,n1,n2,n3,d0,d1,d2,d3;
        upk2(n0, n1, num[j][0]); upk2(n2, n3, num[j][1]);
        upk2(d0, d1, den[j][0]); upk2(d2, d3, den[j][1]);
        float4 r;
        r.x = __fdividef(n0, d0 == 0.f ? 1.f : d0);
        r.y = __fdividef(n1, d1 == 0.f ? 1.f : d1);
        r.z = __fdividef(n2, d2 == 0.f ? 1.f : d2);
        r.w = __fdividef(n3, d3 == 0.f ? 1.f : d3);
        *(float4*)&news[l*32 + h4] = r;
    }
    __syncwarp();

    for (int oi = lane; oi < L1D*OUTD; oi += 32) {
        int l = oi >> 4, o = oi & 15;
        float acc = __ldg(&b_out[o]);
        #pragma unroll
        for (int h = 0; h < HID; h++)
            acc = fmaf(news[l*32 + h], __ldg(&W_out[h*16 + o]), acc);
        out[((b*L1D + l)*N_NODES + n)*OUTD + o] = acc;
    }
}

// ---------------- launch ----------------
extern "C" void kernel_launch(void* const* d_in, const int* in_sizes, int n_in,
                              void* d_out, int out_size) {
    const float* long_states = (const float*)d_in[0];   // [B,N,REF]
    const float* short_in    = (const float*)d_in[1];   // [B,L1,N,IN]
    const int*   src         = (const int*)d_in[2];
    const int*   dst         = (const int*)d_in[3];
    const float* W_in        = (const float*)d_in[4];
    const float* b_in        = (const float*)d_in[5];
    const float* W_metaW     = (const float*)d_in[6];
    const float* b_metaW     = (const float*)d_in[7];
    const float* W_metab     = (const float*)d_in[8];
    const float* b_metab     = (const float*)d_in[9];
    const float* W_out       = (const float*)d_in[10];
    const float* b_out       = (const float*)d_in[11];
    float* out = (float*)d_out;

    cudaFuncSetAttribute(k_main, cudaFuncAttributeMaxDynamicSharedMemorySize, SMEM_MAIN);

    k_statehist_meta<<<N_NODES + 4000, 256>>>(short_in, W_in, b_in, dst,
                                              long_states, W_metaW, b_metaW);
    k_scan<<<1, 1024>>>();
    k_pmbscatter<<<NB, 128>>>(dst, long_states, W_metab, b_metab);
    k_main<<<N_NODES, 128, SMEM_MAIN>>>(src, W_out, b_out, out);
}

// round 9
// speedup vs baseline: 1.1301x; 1.1301x over previous
#include <cuda_runtime.h>

#define N_NODES 2000
#define N_EDGES 16000
#define BB 4
#define L1D 12
#define IN_DIM 16
#define REF 32
#define HID 32
#define OUTD 16
#define NB (N_NODES*BB)   // 8000
#define MAXDEG 96

typedef unsigned long long u64;
typedef unsigned int u32;

// ---------------- scratch (device globals; no allocation) ----------------
__device__ float g_state[NB*L1D*HID];   // [n][b][l][h]
__device__ float g_A[NB*2048];          // A[nb][c], c=k*32+h, k=0..63 (b_metaW folded in)
__device__ float g_Bm[NB*2048];         // Bm[nb][c]
__device__ float g_P1[NB*L1D*HID];      // state @ A1
__device__ float g_P4[NB*L1D*HID];      // state @ B2
__device__ float g_mbs[NB*HID];
__device__ float g_mbd[NB*HID];
__device__ int   g_counts[N_NODES];     // zero at load; k_scan re-zeroes each replay
__device__ int   g_cursor[N_NODES];
__device__ int   g_offsets[N_NODES+1];
__device__ int   g_sorted[N_EDGES];

// ---------------- f32x2 packed helpers (Blackwell) ----------------
__device__ __forceinline__ u64 pk2(float lo, float hi) {
    u64 r; asm("mov.b64 %0, {%1,%2};" : "=l"(r) : "f"(lo), "f"(hi)); return r;
}
__device__ __forceinline__ u64 pk2s(float v) { return pk2(v, v); }
__device__ __forceinline__ void upk2(float& lo, float& hi, u64 v) {
    asm("mov.b64 {%0,%1}, %2;" : "=f"(lo), "=f"(hi) : "l"(v));
}
__device__ __forceinline__ u64 fma2(u64 a, u64 b, u64 c) {
    u64 d; asm("fma.rn.f32x2 %0, %1, %2, %3;" : "=l"(d) : "l"(a), "l"(b), "l"(c)); return d;
}
__device__ __forceinline__ u64 add2(u64 a, u64 b) {
    u64 d; asm("add.rn.f32x2 %0, %1, %2;" : "=l"(d) : "l"(a), "l"(b)); return d;
}

// ---------------- cp.async helpers ----------------
__device__ __forceinline__ void cpa16(u32 s, const void* g) {
    asm volatile("cp.async.cg.shared.global [%0], [%1], 16;" :: "r"(s), "l"(g));
}
__device__ __forceinline__ void cpcommit() {
    asm volatile("cp.async.commit_group;");
}
template<int N> __device__ __forceinline__ void cpwait() {
    asm volatile("cp.async.wait_group %0;" :: "n"(N));
}

// ---------------- L1: fused state(+hist) | meta GEMM (R7 4x8-tile geometry) ----------------
// grid 6000 x 128 threads:
//   blocks [0,2000): state for node bx + histogram for edges [8*bx, 8*bx+8)
//   blocks [2000,6000): meta tile m = bx-2000: nb0 = (m%250)*32, c0 = (m/250)*128
__global__ void __launch_bounds__(128) k_statehistmeta(
        const float* __restrict__ x, const float* __restrict__ W_in,
        const float* __restrict__ b_in, const int* __restrict__ dst,
        const float* __restrict__ mk, const float* __restrict__ W,
        const float* __restrict__ bW) {
    __shared__ __align__(16) float shm[9216];   // 36 KB: meta needs mks|wA|wB
    int t = threadIdx.x;
    int bx = blockIdx.x;

    if (bx < N_NODES) {
        // ---- state + hist (128 threads) ----
        int n = bx;
        float* xs = shm;            // 768
        float* ws = shm + 768;      // 512
        float* bs = shm + 1280;     // 32
        if (t < 8) atomicAdd(&g_counts[dst[8*n + t]], 1);
        for (int i = t; i < IN_DIM*HID; i += 128) ws[i] = W_in[i];
        if (t < HID) bs[t] = b_in[t];
        for (int i = t; i < BB*L1D*IN_DIM; i += 128) {
            int bl = i / IN_DIM, ii = i % IN_DIM;
            int b = bl / L1D, l = bl % L1D;
            xs[i] = x[((b*L1D + l)*N_NODES + n)*IN_DIM + ii];
        }
        __syncthreads();
        for (int o = t; o < BB*L1D*HID; o += 128) {
            int h = o % HID, bl = o / HID;
            float acc = bs[h];
            #pragma unroll
            for (int i = 0; i < IN_DIM; i++)
                acc = fmaf(xs[bl*IN_DIM + i], ws[i*HID + h], acc);
            g_state[n*(BB*L1D*HID) + o] = acc;
        }
        return;
    }

    // ---- meta GEMM tile (exact R7 geometry: 128 thr, 4 rows x 8 cols per thread) ----
    int m = bx - N_NODES;
    int nb0 = (m % 250) * 32;
    int c0  = (m / 250) * 128;
    float* mks = shm;          // 32x32
    float* wA  = shm + 1024;   // 32x128
    float* wB  = shm + 5120;   // 32x128
    for (int i = t; i < 1024; i += 128) {
        int row = i >> 5, r = i & 31;
        int nb = nb0 + row, n = nb >> 2, b = nb & 3;
        mks[i] = mk[(b*N_NODES + n)*REF + r];
    }
    for (int i = t; i < 1024; i += 128) {
        int r = (i*4) >> 7, c = (i*4) & 127;
        *(float4*)&wA[r*128 + c] = *(const float4*)&W[r*2048 + c0 + c];
        *(float4*)&wB[r*128 + c] = *(const float4*)&W[(r + REF)*2048 + c0 + c];
    }
    __syncthreads();
    int tc = t & 15;          // 16 col-groups x 8 cols
    int tr = t >> 4;          // 8 row-groups x 4 rows
    int row0 = tr * 4, col0 = tc * 8;
    u64 accA[4][4], accB[4][4];
    #pragma unroll
    for (int i = 0; i < 4; i++)
        #pragma unroll
        for (int j = 0; j < 4; j++) { accA[i][j] = 0ull; accB[i][j] = 0ull; }
    #pragma unroll 8
    for (int r = 0; r < REF; r++) {
        ulonglong2 wa0 = *(const ulonglong2*)&wA[r*128 + col0];
        ulonglong2 wa1 = *(const ulonglong2*)&wA[r*128 + col0 + 4];
        ulonglong2 wb0 = *(const ulonglong2*)&wB[r*128 + col0];
        ulonglong2 wb1 = *(const ulonglong2*)&wB[r*128 + col0 + 4];
        #pragma unroll
        for (int i = 0; i < 4; i++) {
            u64 a = pk2s(mks[(row0 + i)*32 + r]);
            accA[i][0] = fma2(a, wa0.x, accA[i][0]);
            accA[i][1] = fma2(a, wa0.y, accA[i][1]);
            accA[i][2] = fma2(a, wa1.x, accA[i][2]);
            accA[i][3] = fma2(a, wa1.y, accA[i][3]);
            accB[i][0] = fma2(a, wb0.x, accB[i][0]);
            accB[i][1] = fma2(a, wb0.y, accB[i][1]);
            accB[i][2] = fma2(a, wb1.x, accB[i][2]);
            accB[i][3] = fma2(a, wb1.y, accB[i][3]);
        }
    }
    ulonglong2 bv0 = *(const ulonglong2*)&bW[c0 + col0];
    ulonglong2 bv1 = *(const ulonglong2*)&bW[c0 + col0 + 4];
    #pragma unroll
    for (int i = 0; i < 4; i++) {
        int nb = nb0 + row0 + i;
        ulonglong2 oa0, oa1, ob0, ob1;
        oa0.x = add2(accA[i][0], bv0.x); oa0.y = add2(accA[i][1], bv0.y);
        oa1.x = add2(accA[i][2], bv1.x); oa1.y = add2(accA[i][3], bv1.y);
        ob0.x = accB[i][0]; ob0.y = accB[i][1];
        ob1.x = accB[i][2]; ob1.y = accB[i][3];
        *(ulonglong2*)&g_A[nb*2048 + c0 + col0]      = oa0;
        *(ulonglong2*)&g_A[nb*2048 + c0 + col0 + 4]  = oa1;
        *(ulonglong2*)&g_Bm[nb*2048 + c0 + col0]     = ob0;
        *(ulonglong2*)&g_Bm[nb*2048 + c0 + col0 + 4] = ob1;
    }
}

// ---------------- L2: scan (also re-zeroes g_counts for next replay) ----------------
__global__ void k_scan() {
    __shared__ int sb[1024];
    int t = threadIdx.x;
    int i0 = 2*t, i1 = 2*t + 1;
    int a0 = (i0 < N_NODES) ? g_counts[i0] : 0;
    int a1 = (i1 < N_NODES) ? g_counts[i1] : 0;
    sb[t] = a0 + a1;
    __syncthreads();
    for (int off = 1; off < 1024; off <<= 1) {
        int v = (t >= off) ? sb[t - off] : 0;
        __syncthreads();
        sb[t] += v;
        __syncthreads();
    }
    int excl = sb[t] - (a0 + a1);
    if (i0 < N_NODES) { g_offsets[i0] = excl;      g_cursor[i0] = excl;      g_counts[i0] = 0; }
    if (i1 < N_NODES) { g_offsets[i1] = excl + a0; g_cursor[i1] = excl + a0; g_counts[i1] = 0; }
    if (t == 1023) g_offsets[N_NODES] = sb[1023];
}

// ---------------- L3: fused pmb + scatter ----------------
// grid 8000 x 128: block nb does pmb(nb); blocks < 500 also scatter 32 edges each.
__global__ void __launch_bounds__(128) k_pmbscatter(
        const int* __restrict__ dst,
        const float* __restrict__ mk, const float* __restrict__ Wmb,
        const float* __restrict__ bmb) {
    int nb = blockIdx.x, n = nb >> 2, b = nb & 3;
    int t = threadIdx.x;  // 128

    if (nb < 500 && t < 32) {
        int e = nb * 32 + t;
        if (e < N_EDGES) {
            int d = dst[e];
            int pos = atomicAdd(&g_cursor[d], 1);
            g_sorted[pos] = e;   // arbitrary bin order; k_main rank-sorts
        }
    }

    __shared__ float st[L1D*HID];
    __shared__ float A1[1024];
    __shared__ float B2[1024];
    __shared__ float mks[REF];
    {
        const float4* ps = reinterpret_cast<const float4*>(&g_state[nb*L1D*HID]);
        float4* ss = reinterpret_cast<float4*>(st);
        for (int i = t; i < (L1D*HID)/4; i += 128) ss[i] = ps[i];
        const float4* pa = reinterpret_cast<const float4*>(&g_A[nb*2048]);
        const float4* pb = reinterpret_cast<const float4*>(&g_Bm[nb*2048 + 1024]);
        float4* sa = reinterpret_cast<float4*>(A1);
        float4* sb = reinterpret_cast<float4*>(B2);
        for (int i = t; i < 256; i += 128) { sa[i] = pa[i]; sb[i] = pb[i]; }
    }
    if (t < REF) mks[t] = mk[(b*N_NODES + n)*REF + t];
    __syncthreads();
    int h = t & 31, l0 = t >> 5;
    #pragma unroll
    for (int j = 0; j < 3; j++) {
        int l = l0 + 4*j;
        float p1 = 0.f, p4 = 0.f;
        #pragma unroll
        for (int k = 0; k < HID; k++) {
            float s = st[l*HID + k];
            p1 = fmaf(s, A1[k*32 + h], p1);
            p4 = fmaf(s, B2[k*32 + h], p4);
        }
        g_P1[nb*(L1D*HID) + l*32 + h] = p1;
        g_P4[nb*(L1D*HID) + l*32 + h] = p4;
    }
    if (t < HID) {
        float s1 = 0.f, s2 = bmb[t];
        #pragma unroll
        for (int r = 0; r < REF; r++) {
            s1 = fmaf(mks[r], Wmb[r*HID + t], s1);
            s2 = fmaf(mks[r], Wmb[(r + REF)*HID + t], s2);
        }
        g_mbs[nb*HID + t] = s1;
        g_mbd[nb*HID + t] = s2;
    }
}

// ---------------- L4: k_main — block = node n; warp = batch b; warp owns whole bin ----------------
#define PWW 4368
#define SMEM_MAIN ((192 + 4*PWW)*4)   // 70656 bytes -> 3 blocks/SM

__global__ void __launch_bounds__(128, 3) k_main(const int* __restrict__ src,
                                                 const float* __restrict__ W_out,
                                                 const float* __restrict__ b_out,
                                                 float* __restrict__ out) {
    extern __shared__ __align__(16) float sh[];
    int* ekeys = (int*)sh;
    int* slist = (int*)sh + 96;

    int t = threadIdx.x, wid = t >> 5, lane = t & 31;
    int n = blockIdx.x, b = wid;
    int nbd = n*4 + b;
    int es = g_offsets[n];
    int deg = g_offsets[n+1] - es;
    int degc = (deg < MAXDEG) ? deg : MAXDEG;

    if (t < degc) ekeys[t] = g_sorted[es + t];

    float* W   = sh + 192 + wid*PWW;
    float* B1d  = W;            // 1024
    float* A2b  = W + 1024;     // 2 x 1024
    float* stsS = W + 3072;     // 2 x 432
    float* stds = W + 3936;     // 432

    for (int i = lane; i < 256; i += 32)
        ((float4*)B1d)[i] = ((const float4*)&g_Bm[(size_t)nbd*2048])[i];
    for (int i = lane; i < 96; i += 32) {
        int l = i >> 3, c4 = (i & 7) * 4;
        *(float4*)&stds[l*36 + c4] = ((const float4*)&g_state[nbd*384])[i];
    }
    __syncthreads();

    if (t < degc) {
        int key = ekeys[t], r = 0;
        for (int j = 0; j < degc; j++) r += (ekeys[j] < key);
        slist[r] = src[key];
    }
    __syncthreads();

    int lg = lane >> 3, hg = lane & 7, h4 = hg * 4;
    int l0 = lg * 3;

    float4 p4m[3];
    {
        float4 md = *(const float4*)&g_mbd[nbd*32 + h4];
        #pragma unroll
        for (int j = 0; j < 3; j++) {
            float4 a = *(const float4*)&g_P4[nbd*384 + (l0 + j)*32 + h4];
            p4m[j].x = a.x + md.x; p4m[j].y = a.y + md.y;
            p4m[j].z = a.z + md.z; p4m[j].w = a.w + md.w;
        }
    }

    u32 sA2 = (u32)__cvta_generic_to_shared(A2b);
    u32 sSt = (u32)__cvta_generic_to_shared(stsS);

    u64 num[3][2], den[3][2];
    #pragma unroll
    for (int j = 0; j < 3; j++) { num[j][0]=num[j][1]=den[j][0]=den[j][1]=0ull; }

    float4 p1c[3], mbc;

    auto computeEdge = [&](int v) {
        float* A2v = A2b + v*1024;
        float* stv = stsS + v*432;
        u64 att[3][2];
        #pragma unroll
        for (int j = 0; j < 3; j++) {
            att[j][0] = pk2(p1c[j].x + p4m[j].x + mbc.x, p1c[j].y + p4m[j].y + mbc.y);
            att[j][1] = pk2(p1c[j].z + p4m[j].z + mbc.z, p1c[j].w + p4m[j].w + mbc.w);
        }
        #pragma unroll
        for (int k4 = 0; k4 < 32; k4 += 4) {
            float4 ssv[3], ddv[3];
            #pragma unroll
            for (int j = 0; j < 3; j++) {
                int l = l0 + j;
                ssv[j] = *(float4*)&stv[l*36 + k4];
                ddv[j] = *(float4*)&stds[l*36 + k4];
            }
            #pragma unroll
            for (int kk = 0; kk < 4; kk++) {
                int k = k4 + kk;
                ulonglong2 bb = *(const ulonglong2*)&B1d[k*32 + h4];
                ulonglong2 aa = *(const ulonglong2*)&A2v[k*32 + h4];
                #pragma unroll
                for (int j = 0; j < 3; j++) {
                    float sf = (kk == 0) ? ssv[j].x : (kk == 1) ? ssv[j].y
                             : (kk == 2) ? ssv[j].z : ssv[j].w;
                    float df = (kk == 0) ? ddv[j].x : (kk == 1) ? ddv[j].y
                             : (kk == 2) ? ddv[j].z : ddv[j].w;
                    u64 ss = pk2s(sf), dd = pk2s(df);
                    att[j][0] = fma2(ss, bb.x, att[j][0]);
                    att[j][1] = fma2(ss, bb.y, att[j][1]);
                    att[j][0] = fma2(dd, aa.x, att[j][0]);
                    att[j][1] = fma2(dd, aa.y, att[j][1]);
                }
            }
        }
        #pragma unroll
        for (int j = 0; j < 3; j++) {
            int l = l0 + j;
            float a0,a1,a2,a3;
            upk2(a0, a1, att[j][0]); upk2(a2, a3, att[j][1]);
            float e0 = __expf(a0), e1 = __expf(a1), e2 = __expf(a2), e3 = __expf(a3);
            u64 ep0 = pk2(e0, e1), ep1 = pk2(e2, e3);
            den[j][0] = add2(den[j][0], ep0);
            den[j][1] = add2(den[j][1], ep1);
            float4 sv = *(float4*)&stv[l*36 + h4];
            num[j][0] = fma2(ep0, pk2(sv.x, sv.y), num[j][0]);
            num[j][1] = fma2(ep1, pk2(sv.z, sv.w), num[j][1]);
        }
    };

    for (int m = 0; m < degc + 1; m++) {
        if (m < degc) {
            int nbs = slist[m]*4 + b;
            int v = m & 1;
            const float* pa = &g_A[(size_t)nbs*2048 + 1024];
            #pragma unroll
            for (int r = 0; r < 8; r++) {
                int c = lane + 32*r;
                cpa16(sA2 + v*4096 + c*16, pa + c*4);
            }
            const float* ps = &g_state[nbs*384];
            #pragma unroll
            for (int r = 0; r < 3; r++) {
                int c = lane + 32*r;
                int l = c >> 3, c4 = (c & 7) * 4;
                cpa16(sSt + v*1728 + (l*36 + c4)*4, ps + c*4);
            }
            cpcommit();
        }
        if (m > 0) {
            if (m < degc) cpwait<1>(); else cpwait<0>();
            __syncwarp();
            computeEdge((m - 1) & 1);
            __syncwarp();
        }
        if (m < degc) {
            int nbs = slist[m]*4 + b;
            #pragma unroll
            for (int j = 0; j < 3; j++)
                p1c[j] = __ldg((const float4*)&g_P1[nbs*384 + (l0 + j)*32 + h4]);
            mbc = __ldg((const float4*)&g_mbs[nbs*32 + h4]);
        }
    }

    // overflow fallback (deg > MAXDEG): synchronous, correct, rare
    for (int i = MAXDEG; i < deg; i++) {
        int nbs = src[g_sorted[es + i]]*4 + b;
        for (int c = lane; c < 256; c += 32)
            ((float4*)A2b)[c] = ((const float4*)&g_A[(size_t)nbs*2048 + 1024])[c];
        for (int c = lane; c < 96; c += 32) {
            int l = c >> 3, c4 = (c & 7) * 4;
            *(float4*)&stsS[l*36 + c4] = ((const float4*)&g_state[nbs*384])[c];
        }
        #pragma unroll
        for (int j = 0; j < 3; j++)
            p1c[j] = __ldg((const float4*)&g_P1[nbs*384 + (l0 + j)*32 + h4]);
        mbc = __ldg((const float4*)&g_mbs[nbs*32 + h4]);
        __syncwarp();
        computeEdge(0);
        __syncwarp();
    }

    float* news = A2b;
    __syncwarp();
    #pragma unroll
    for (int j = 0; j < 3; j++) {
        int l = l0 + j;
        float n0,n1,n2,n3,d0,d1,d2,d3;
        upk2(n0, n1, num[j][0]); upk2(n2, n3, num[j][1]);
        upk2(d0, d1, den[j][0]); upk2(d2, d3, den[j][1]);
        float4 r;
        r.x = __fdividef(n0, d0 == 0.f ? 1.f : d0);
        r.y = __fdividef(n1, d1 == 0.f ? 1.f : d1);
        r.z = __fdividef(n2, d2 == 0.f ? 1.f : d2);
        r.w = __fdividef(n3, d3 == 0.f ? 1.f : d3);
        *(float4*)&news[l*32 + h4] = r;
    }
    __syncwarp();

    for (int oi = lane; oi < L1D*OUTD; oi += 32) {
        int l = oi >> 4, o = oi & 15;
        float acc = __ldg(&b_out[o]);
        #pragma unroll
        for (int h = 0; h < HID; h++)
            acc = fmaf(news[l*32 + h], __ldg(&W_out[h*16 + o]), acc);
        out[((b*L1D + l)*N_NODES + n)*OUTD + o] = acc;
    }
}

// ---------------- launch ----------------
extern "C" void kernel_launch(void* const* d_in, const int* in_sizes, int n_in,
                              void* d_out, int out_size) {
    const float* long_states = (const float*)d_in[0];   // [B,N,REF]
    const float* short_in    = (const float*)d_in[1];   // [B,L1,N,IN]
    const int*   src         = (const int*)d_in[2];
    const int*   dst         = (const int*)d_in[3];
    const float* W_in        = (const float*)d_in[4];
    const float* b_in        = (const float*)d_in[5];
    const float* W_metaW     = (const float*)d_in[6];
    const float* b_metaW     = (const float*)d_in[7];
    const float* W_metab     = (const float*)d_in[8];
    const float* b_metab     = (const float*)d_in[9];
    const float* W_out       = (const float*)d_in[10];
    const float* b_out       = (const float*)d_in[11];
    float* out = (float*)d_out;

    cudaFuncSetAttribute(k_main, cudaFuncAttributeMaxDynamicSharedMemorySize, SMEM_MAIN);

    k_statehistmeta<<<N_NODES + 4000, 128>>>(short_in, W_in, b_in, dst,
                                             long_states, W_metaW, b_metaW);
    k_scan<<<1, 1024>>>();
    k_pmbscatter<<<NB, 128>>>(dst, long_states, W_metab, b_metab);
    k_main<<<N_NODES, 128, SMEM_MAIN>>>(src, W_out, b_out, out);
}

// round 10
// speedup vs baseline: 1.3853x; 1.2258x over previous
#include <cuda_runtime.h>
#include <cuda_fp16.h>

#define N_NODES 2000
#define N_EDGES 16000
#define BB 4
#define L1D 12
#define IN_DIM 16
#define REF 32
#define HID 32
#define OUTD 16
#define NB (N_NODES*BB)   // 8000
#define MAXDEG 96

typedef unsigned long long u64;
typedef unsigned int u32;

// ---------------- scratch (device globals; no allocation) ----------------
__device__ float  g_state[NB*384];   // fp32 state [nb][l*32+h]
__device__ __half g_sth[NB*384];     // fp16 state
__device__ float  g_A1f[NB*1024];    // A1 fp32 (bias incl)  -> pmb
__device__ float  g_B2f[NB*1024];    // B2 fp32              -> pmb
__device__ __half g_A2h[NB*1024];    // A2 fp16 (bias incl)  -> k_main, [k][h]
__device__ __half g_B1h[NB*1024];    // B1 fp16              -> k_main, [k][h]
__device__ float  g_P1m[NB*384];     // P1 + mbs
__device__ float  g_P4m[NB*384];     // P4 + mbd
__device__ int    g_counts[N_NODES]; // zero at load; k_scan re-zeroes each replay
__device__ int    g_cursor[N_NODES];
__device__ int    g_offsets[N_NODES+1];
__device__ int    g_sorted[N_EDGES];

// ---------------- f32x2 packed helpers ----------------
__device__ __forceinline__ u64 pk2(float lo, float hi) {
    u64 r; asm("mov.b64 %0, {%1,%2};" : "=l"(r) : "f"(lo), "f"(hi)); return r;
}
__device__ __forceinline__ u64 pk2s(float v) { return pk2(v, v); }
__device__ __forceinline__ void upk2(float& lo, float& hi, u64 v) {
    asm("mov.b64 {%0,%1}, %2;" : "=f"(lo), "=f"(hi) : "l"(v));
}
__device__ __forceinline__ u64 fma2(u64 a, u64 b, u64 c) {
    u64 d; asm("fma.rn.f32x2 %0, %1, %2, %3;" : "=l"(d) : "l"(a), "l"(b), "l"(c)); return d;
}
__device__ __forceinline__ u64 add2(u64 a, u64 b) {
    u64 d; asm("add.rn.f32x2 %0, %1, %2;" : "=l"(d) : "l"(a), "l"(b)); return d;
}
__device__ __forceinline__ u32 h2u(u64 p) {
    float lo, hi; upk2(lo, hi, p);
    __half2 h = __floats2half2_rn(lo, hi);
    return *reinterpret_cast<u32*>(&h);
}

// ---------------- cp.async / ldmatrix / mma helpers ----------------
__device__ __forceinline__ void cpa16(u32 s, const void* g) {
    asm volatile("cp.async.cg.shared.global [%0], [%1], 16;" :: "r"(s), "l"(g));
}
__device__ __forceinline__ void cpcommit() { asm volatile("cp.async.commit_group;"); }
template<int N> __device__ __forceinline__ void cpwait() {
    asm volatile("cp.async.wait_group %0;" :: "n"(N));
}
__device__ __forceinline__ void ldsm4(u32& r0, u32& r1, u32& r2, u32& r3, u32 addr) {
    asm volatile("ldmatrix.sync.aligned.m8n8.x4.shared.b16 {%0,%1,%2,%3}, [%4];"
        : "=r"(r0), "=r"(r1), "=r"(r2), "=r"(r3) : "r"(addr));
}
__device__ __forceinline__ void ldsm4t(u32& r0, u32& r1, u32& r2, u32& r3, u32 addr) {
    asm volatile("ldmatrix.sync.aligned.m8n8.x4.trans.shared.b16 {%0,%1,%2,%3}, [%4];"
        : "=r"(r0), "=r"(r1), "=r"(r2), "=r"(r3) : "r"(addr));
}
__device__ __forceinline__ void mma16816(float& c0, float& c1, float& c2, float& c3,
                                         u32 a0, u32 a1, u32 a2, u32 a3, u32 b0, u32 b1) {
    asm volatile("mma.sync.aligned.m16n8k16.row.col.f32.f16.f16.f32 "
        "{%0,%1,%2,%3}, {%4,%5,%6,%7}, {%8,%9}, {%0,%1,%2,%3};"
        : "+f"(c0), "+f"(c1), "+f"(c2), "+f"(c3)
        : "r"(a0), "r"(a1), "r"(a2), "r"(a3), "r"(b0), "r"(b1));
}

// ---------------- L1: fused state(+hist) | meta GEMM ----------------
// grid 6000 x 128: blocks [0,2000) state+hist; [2000,6000) meta tiles
__global__ void __launch_bounds__(128) k_statehistmeta(
        const float* __restrict__ x, const float* __restrict__ W_in,
        const float* __restrict__ b_in, const int* __restrict__ dst,
        const float* __restrict__ mk, const float* __restrict__ W,
        const float* __restrict__ bW) {
    __shared__ __align__(16) float shm[9216];
    int t = threadIdx.x;
    int bx = blockIdx.x;

    if (bx < N_NODES) {
        int n = bx;
        float* xs = shm;
        float* ws = shm + 768;
        float* bs = shm + 1280;
        if (t < 8) atomicAdd(&g_counts[dst[8*n + t]], 1);
        for (int i = t; i < IN_DIM*HID; i += 128) ws[i] = W_in[i];
        if (t < HID) bs[t] = b_in[t];
        for (int i = t; i < BB*L1D*IN_DIM; i += 128) {
            int bl = i / IN_DIM, ii = i % IN_DIM;
            int b = bl / L1D, l = bl % L1D;
            xs[i] = x[((b*L1D + l)*N_NODES + n)*IN_DIM + ii];
        }
        __syncthreads();
        for (int o = t; o < BB*L1D*HID; o += 128) {
            int h = o % HID, bl = o / HID;
            float acc = bs[h];
            #pragma unroll
            for (int i = 0; i < IN_DIM; i++)
                acc = fmaf(xs[bl*IN_DIM + i], ws[i*HID + h], acc);
            g_state[n*(BB*L1D*HID) + o] = acc;
            g_sth[n*(BB*L1D*HID) + o] = __float2half_rn(acc);
        }
        return;
    }

    int m = bx - N_NODES;
    int nb0 = (m % 250) * 32;
    int c0  = (m / 250) * 128;
    float* mks = shm;
    float* wA  = shm + 1024;
    float* wB  = shm + 5120;
    for (int i = t; i < 1024; i += 128) {
        int row = i >> 5, r = i & 31;
        int nb = nb0 + row, n = nb >> 2, b = nb & 3;
        mks[i] = mk[(b*N_NODES + n)*REF + r];
    }
    for (int i = t; i < 1024; i += 128) {
        int r = (i*4) >> 7, c = (i*4) & 127;
        *(float4*)&wA[r*128 + c] = *(const float4*)&W[r*2048 + c0 + c];
        *(float4*)&wB[r*128 + c] = *(const float4*)&W[(r + REF)*2048 + c0 + c];
    }
    __syncthreads();
    int tc = t & 15, tr = t >> 4;
    int row0 = tr * 4, col0 = tc * 8;
    u64 accA[4][4], accB[4][4];
    #pragma unroll
    for (int i = 0; i < 4; i++)
        #pragma unroll
        for (int j = 0; j < 4; j++) { accA[i][j] = 0ull; accB[i][j] = 0ull; }
    #pragma unroll 8
    for (int r = 0; r < REF; r++) {
        ulonglong2 wa0 = *(const ulonglong2*)&wA[r*128 + col0];
        ulonglong2 wa1 = *(const ulonglong2*)&wA[r*128 + col0 + 4];
        ulonglong2 wb0 = *(const ulonglong2*)&wB[r*128 + col0];
        ulonglong2 wb1 = *(const ulonglong2*)&wB[r*128 + col0 + 4];
        #pragma unroll
        for (int i = 0; i < 4; i++) {
            u64 a = pk2s(mks[(row0 + i)*32 + r]);
            accA[i][0] = fma2(a, wa0.x, accA[i][0]);
            accA[i][1] = fma2(a, wa0.y, accA[i][1]);
            accA[i][2] = fma2(a, wa1.x, accA[i][2]);
            accA[i][3] = fma2(a, wa1.y, accA[i][3]);
            accB[i][0] = fma2(a, wb0.x, accB[i][0]);
            accB[i][1] = fma2(a, wb0.y, accB[i][1]);
            accB[i][2] = fma2(a, wb1.x, accB[i][2]);
            accB[i][3] = fma2(a, wb1.y, accB[i][3]);
        }
    }
    ulonglong2 bv0 = *(const ulonglong2*)&bW[c0 + col0];
    ulonglong2 bv1 = *(const ulonglong2*)&bW[c0 + col0 + 4];
    #pragma unroll
    for (int i = 0; i < 4; i++) {
        int nb = nb0 + row0 + i;
        u64 oa0 = add2(accA[i][0], bv0.x), oa1 = add2(accA[i][1], bv0.y);
        u64 oa2 = add2(accA[i][2], bv1.x), oa3 = add2(accA[i][3], bv1.y);
        if (c0 < 1024) {
            int off = nb*1024 + c0 + col0;
            ulonglong2 fa0 = {oa0, oa1}, fa1 = {oa2, oa3};
            *(ulonglong2*)&g_A1f[off]     = fa0;
            *(ulonglong2*)&g_A1f[off + 4] = fa1;
            uint4 hb = { h2u(accB[i][0]), h2u(accB[i][1]), h2u(accB[i][2]), h2u(accB[i][3]) };
            *(uint4*)&g_B1h[off] = hb;
        } else {
            int off = nb*1024 + (c0 - 1024) + col0;
            uint4 ha = { h2u(oa0), h2u(oa1), h2u(oa2), h2u(oa3) };
            *(uint4*)&g_A2h[off] = ha;
            ulonglong2 fb0 = {accB[i][0], accB[i][1]}, fb1 = {accB[i][2], accB[i][3]};
            *(ulonglong2*)&g_B2f[off]     = fb0;
            *(ulonglong2*)&g_B2f[off + 4] = fb1;
        }
    }
}

// ---------------- L2: scan (re-zeroes g_counts for next replay) ----------------
__global__ void k_scan() {
    __shared__ int sb[1024];
    int t = threadIdx.x;
    int i0 = 2*t, i1 = 2*t + 1;
    int a0 = (i0 < N_NODES) ? g_counts[i0] : 0;
    int a1 = (i1 < N_NODES) ? g_counts[i1] : 0;
    sb[t] = a0 + a1;
    __syncthreads();
    for (int off = 1; off < 1024; off <<= 1) {
        int v = (t >= off) ? sb[t - off] : 0;
        __syncthreads();
        sb[t] += v;
        __syncthreads();
    }
    int excl = sb[t] - (a0 + a1);
    if (i0 < N_NODES) { g_offsets[i0] = excl;      g_cursor[i0] = excl;      g_counts[i0] = 0; }
    if (i1 < N_NODES) { g_offsets[i1] = excl + a0; g_cursor[i1] = excl + a0; g_counts[i1] = 0; }
    if (t == 1023) g_offsets[N_NODES] = sb[1023];
}

// ---------------- L3: fused pmb (+ scatter) ----------------
__global__ void __launch_bounds__(128) k_pmbscatter(
        const int* __restrict__ dst,
        const float* __restrict__ mk, const float* __restrict__ Wmb,
        const float* __restrict__ bmb) {
    int nb = blockIdx.x, n = nb >> 2, b = nb & 3;
    int t = threadIdx.x;

    if (nb < 500 && t < 32) {
        int e = nb * 32 + t;
        if (e < N_EDGES) {
            int d = dst[e];
            int pos = atomicAdd(&g_cursor[d], 1);
            g_sorted[pos] = e;
        }
    }

    __shared__ float st[L1D*HID];
    __shared__ float A1[1024];
    __shared__ float B2[1024];
    __shared__ float mks[REF];
    __shared__ float mbsh[HID], mbdh[HID];
    {
        const float4* ps = (const float4*)&g_state[nb*384];
        float4* ss = (float4*)st;
        for (int i = t; i < 96; i += 128) ss[i] = ps[i];
        const float4* pa = (const float4*)&g_A1f[nb*1024];
        const float4* pb = (const float4*)&g_B2f[nb*1024];
        float4* sa = (float4*)A1;
        float4* sb = (float4*)B2;
        for (int i = t; i < 256; i += 128) { sa[i] = pa[i]; sb[i] = pb[i]; }
    }
    if (t < REF) mks[t] = mk[(b*N_NODES + n)*REF + t];
    __syncthreads();
    if (t < HID) {
        float s1 = 0.f, s2 = bmb[t];
        #pragma unroll
        for (int r = 0; r < REF; r++) {
            s1 = fmaf(mks[r], Wmb[r*HID + t], s1);
            s2 = fmaf(mks[r], Wmb[(r + REF)*HID + t], s2);
        }
        mbsh[t] = s1; mbdh[t] = s2;
    }
    __syncthreads();
    int h = t & 31, l0 = t >> 5;
    #pragma unroll
    for (int j = 0; j < 3; j++) {
        int l = l0 + 4*j;
        float p1 = 0.f, p4 = 0.f;
        #pragma unroll
        for (int k = 0; k < HID; k++) {
            float s = st[l*HID + k];
            p1 = fmaf(s, A1[k*32 + h], p1);
            p4 = fmaf(s, B2[k*32 + h], p4);
        }
        g_P1m[nb*384 + l*32 + h] = p1 + mbsh[h];
        g_P4m[nb*384 + l*32 + h] = p4 + mbdh[h];
    }
}

// ---------------- L4: k_main — tensor-core edge attention ----------------
// per-warp smem bytes: B1s 2048 | dds 1024 | ssb 2x1024 | A2b 2x2048 | p1b 2x2048
#define PWB 13312
#define SMEM_MAIN (768 + 4*PWB)   // 54016 bytes -> 4 blocks/SM

__global__ void __launch_bounds__(128, 4) k_main(const int* __restrict__ src,
                                                 const float* __restrict__ W_out,
                                                 const float* __restrict__ b_out,
                                                 float* __restrict__ out) {
    extern __shared__ __align__(16) char sh[];
    int* ekeys = (int*)sh;              // 96
    int* slist = (int*)(sh + 384);      // 96

    int t = threadIdx.x, wid = t >> 5, lane = t & 31;
    int n = blockIdx.x, b = wid;
    int nbd = n*4 + b;
    int es = g_offsets[n];
    int deg = g_offsets[n+1] - es;
    int degc = (deg < MAXDEG) ? deg : MAXDEG;

    if (t < degc) ekeys[t] = g_sorted[es + t];

    char* wb = sh + 768 + wid*PWB;
    __half* B1s = (__half*)wb;                 // [k][h] 32x32
    __half* dds = (__half*)(wb + 2048);        // [l][k] 16x32 (rows 12-15 zero)
    __half* ssb = (__half*)(wb + 3072);        // 2 x [l][k] 16x32
    __half* A2b = (__half*)(wb + 5120);        // 2 x [k][h] 32x32
    float*  p1b = (float*)(wb + 9216);         // 2 x [l][h] 16x32 (rows 12-15 zero)
    float*  news = (float*)(wb + 5120);        // alias over A2b after loop

    // prologue copies (per warp)
    {
        const uint4* pb1 = (const uint4*)&g_B1h[(size_t)nbd*1024];
        #pragma unroll
        for (int i = lane; i < 128; i += 32) ((uint4*)B1s)[i] = pb1[i];
        const uint4* pdd = (const uint4*)&g_sth[(size_t)nbd*384];
        if (lane < 48) { if (lane < 32) ((uint4*)dds)[lane] = pdd[lane]; }
        if (lane < 16) ((uint4*)dds)[32 + lane] = pdd[32 + lane];
        uint4 z = {0,0,0,0};
        if (lane < 16) ((uint4*)dds)[48 + lane] = z;
        #pragma unroll
        for (int v = 0; v < 2; v++) {
            if (lane < 16) ((uint4*)(ssb + v*512))[48 + lane] = z;
            if (lane < 32) { ((float4*)(p1b + v*512))[96 + lane] = make_float4(0,0,0,0); }
        }
    }
    __syncthreads();

    if (t < degc) {
        int key = ekeys[t], r = 0;
        for (int j = 0; j < degc; j++) r += (ekeys[j] < key);
        slist[r] = src[key];
    }
    __syncthreads();

    // fragment-lane geometry
    int qr = lane & 7, q = lane >> 3;
    u32 offM = (u32)((qr + (q & 1)*8)*64 + (q >> 1)*16);   // shared for A-type and B-type ldmatrix
    int r0 = lane >> 2;            // C-frag row (0..7)
    int cbase = 2*(lane & 3);

    u32 sB1 = (u32)__cvta_generic_to_shared(B1s);
    u32 sDD = (u32)__cvta_generic_to_shared(dds);
    u32 sSS = (u32)__cvta_generic_to_shared(ssb);
    u32 sA2 = (u32)__cvta_generic_to_shared(A2b);
    u32 sP1 = (u32)__cvta_generic_to_shared(p1b);

    // fixed fragments: B1 (8 frags), dd (2 tiles)
    u32 b1f[2][4][2];
    #pragma unroll
    for (int s = 0; s < 2; s++)
        #pragma unroll
        for (int p = 0; p < 2; p++) {
            u32 r0_, r1_, r2_, r3_;
            ldsm4t(r0_, r1_, r2_, r3_, sB1 + offM + s*1024 + p*32);
            b1f[s][p*2][0] = r0_;   b1f[s][p*2][1] = r1_;
            b1f[s][p*2+1][0] = r2_; b1f[s][p*2+1][1] = r3_;
        }
    u32 ddf[2][4];
    #pragma unroll
    for (int s = 0; s < 2; s++)
        ldsm4(ddf[s][0], ddf[s][1], ddf[s][2], ddf[s][3], sDD + offM + s*32);

    // fixed base: P4m at C positions
    float p4r[4][4];
    #pragma unroll
    for (int j = 0; j < 4; j++) {
        int col = 8*j + cbase;
        float2 lo = *(const float2*)&g_P4m[nbd*384 + r0*32 + col];
        p4r[j][0] = lo.x; p4r[j][1] = lo.y;
        if (r0 < 4) {
            float2 hi = *(const float2*)&g_P4m[nbd*384 + (r0+8)*32 + col];
            p4r[j][2] = hi.x; p4r[j][3] = hi.y;
        } else { p4r[j][2] = 0.f; p4r[j][3] = 0.f; }
    }

    float den[4][4], num[4][4];
    #pragma unroll
    for (int j = 0; j < 4; j++)
        #pragma unroll
        for (int i = 0; i < 4; i++) { den[j][i] = 0.f; num[j][i] = 0.f; }

    auto stageEdge = [&](int nbs, int v) {
        const char* pa = (const char*)&g_A2h[(size_t)nbs*1024];
        u32 da = sA2 + v*2048;
        #pragma unroll
        for (int r = 0; r < 4; r++) {
            int c = lane + 32*r;
            cpa16(da + c*16, pa + c*16);
        }
        const char* ps = (const char*)&g_sth[(size_t)nbs*384];   // 768 B
        u32 dsa = sSS + v*1024;
        cpa16(dsa + lane*16, ps + lane*16);
        if (lane < 16) cpa16(dsa + (32+lane)*16, ps + (32+lane)*16);
        const char* pp = (const char*)&g_P1m[(size_t)nbs*384];   // 1536 B
        u32 dp = sP1 + v*2048;
        #pragma unroll
        for (int r = 0; r < 3; r++) {
            int c = lane + 32*r;
            cpa16(dp + c*16, pp + c*16);
        }
    };

    auto computeEdge = [&](int v) {
        __half* ssv = ssb + v*512;
        float*  p1v = p1b + v*512;
        u32 ssbase = sSS + v*1024;
        u32 a2base = sA2 + v*2048;
        u32 ssf[2][4];
        #pragma unroll
        for (int s = 0; s < 2; s++)
            ldsm4(ssf[s][0], ssf[s][1], ssf[s][2], ssf[s][3], ssbase + offM + s*32);
        u32 a2f[2][4][2];
        #pragma unroll
        for (int s = 0; s < 2; s++)
            #pragma unroll
            for (int p = 0; p < 2; p++) {
                u32 r0_, r1_, r2_, r3_;
                ldsm4t(r0_, r1_, r2_, r3_, a2base + offM + s*1024 + p*32);
                a2f[s][p*2][0] = r0_;   a2f[s][p*2][1] = r1_;
                a2f[s][p*2+1][0] = r2_; a2f[s][p*2+1][1] = r3_;
            }
        #pragma unroll
        for (int j = 0; j < 4; j++) {
            float c0 = 0.f, c1 = 0.f, c2 = 0.f, c3 = 0.f;
            mma16816(c0, c1, c2, c3, ssf[0][0], ssf[0][1], ssf[0][2], ssf[0][3],
                     b1f[0][j][0], b1f[0][j][1]);
            mma16816(c0, c1, c2, c3, ssf[1][0], ssf[1][1], ssf[1][2], ssf[1][3],
                     b1f[1][j][0], b1f[1][j][1]);
            mma16816(c0, c1, c2, c3, ddf[0][0], ddf[0][1], ddf[0][2], ddf[0][3],
                     a2f[0][j][0], a2f[0][j][1]);
            mma16816(c0, c1, c2, c3, ddf[1][0], ddf[1][1], ddf[1][2], ddf[1][3],
                     a2f[1][j][0], a2f[1][j][1]);
            int col = 8*j + cbase;
            float2 plo = *(const float2*)&p1v[r0*32 + col];
            float2 phi = *(const float2*)&p1v[(r0+8)*32 + col];   // rows 12-15 zeroed
            float a0 = c0 + plo.x + p4r[j][0];
            float a1 = c1 + plo.y + p4r[j][1];
            float a2_ = c2 + phi.x + p4r[j][2];
            float a3 = c3 + phi.y + p4r[j][3];
            float w0 = __expf(a0), w1 = __expf(a1), w2 = __expf(a2_), w3 = __expf(a3);
            den[j][0] += w0; den[j][1] += w1; den[j][2] += w2; den[j][3] += w3;
            __half2 hlo = *(const __half2*)&ssv[r0*32 + col];
            __half2 hhi = *(const __half2*)&ssv[(r0+8)*32 + col];  // rows 12-15 zero
            float2 flo = __half22float2(hlo), fhi = __half22float2(hhi);
            num[j][0] = fmaf(w0, flo.x, num[j][0]);
            num[j][1] = fmaf(w1, flo.y, num[j][1]);
            num[j][2] = fmaf(w2, fhi.x, num[j][2]);
            num[j][3] = fmaf(w3, fhi.y, num[j][3]);
        }
    };

    // pipelined main loop over this warp's whole bin
    for (int m = 0; m < degc + 1; m++) {
        if (m < degc) {
            stageEdge(slist[m]*4 + b, m & 1);
            cpcommit();
        }
        if (m > 0) {
            if (m < degc) cpwait<1>(); else cpwait<0>();
            __syncwarp();
            computeEdge((m - 1) & 1);
            __syncwarp();
        }
    }

    // overflow fallback (deg > MAXDEG): synchronous, rare
    for (int i = MAXDEG; i < deg; i++) {
        int nbs = src[g_sorted[es + i]]*4 + b;
        stageEdge(nbs, 0);
        cpcommit();
        cpwait<0>();
        __syncwarp();
        computeEdge(0);
        __syncwarp();
    }
    __syncwarp();

    // finalize softmax into news (aliases A2b; staging is dead now)
    #pragma unroll
    for (int j = 0; j < 4; j++) {
        int col = 8*j + cbase;
        float d0 = den[j][0], d1 = den[j][1], d2 = den[j][2], d3 = den[j][3];
        float2 lo;
        lo.x = __fdividef(num[j][0], d0 == 0.f ? 1.f : d0);
        lo.y = __fdividef(num[j][1], d1 == 0.f ? 1.f : d1);
        *(float2*)&news[r0*32 + col] = lo;
        if (r0 < 4) {
            float2 hi;
            hi.x = __fdividef(num[j][2], d2 == 0.f ? 1.f : d2);
            hi.y = __fdividef(num[j][3], d3 == 0.f ? 1.f : d3);
            *(float2*)&news[(r0+8)*32 + col] = hi;
        }
    }
    __syncwarp();

    // output projection
    for (int oi = lane; oi < L1D*OUTD; oi += 32) {
        int l = oi >> 4, o = oi & 15;
        float acc = __ldg(&b_out[o]);
        #pragma unroll
        for (int h = 0; h < HID; h++)
            acc = fmaf(news[l*32 + h], __ldg(&W_out[h*16 + o]), acc);
        out[((b*L1D + l)*N_NODES + n)*OUTD + o] = acc;
    }
}

// ---------------- launch ----------------
extern "C" void kernel_launch(void* const* d_in, const int* in_sizes, int n_in,
                              void* d_out, int out_size) {
    const float* long_states = (const float*)d_in[0];
    const float* short_in    = (const float*)d_in[1];
    const int*   src         = (const int*)d_in[2];
    const int*   dst         = (const int*)d_in[3];
    const float* W_in        = (const float*)d_in[4];
    const float* b_in        = (const float*)d_in[5];
    const float* W_metaW     = (const float*)d_in[6];
    const float* b_metaW     = (const float*)d_in[7];
    const float* W_metab     = (const float*)d_in[8];
    const float* b_metab     = (const float*)d_in[9];
    const float* W_out       = (const float*)d_in[10];
    const float* b_out       = (const float*)d_in[11];
    float* out = (float*)d_out;

    cudaFuncSetAttribute(k_main, cudaFuncAttributeMaxDynamicSharedMemorySize, SMEM_MAIN);

    k_statehistmeta<<<N_NODES + 4000, 128>>>(short_in, W_in, b_in, dst,
                                             long_states, W_metaW, b_metaW);
    k_scan<<<1, 1024>>>();
    k_pmbscatter<<<NB, 128>>>(dst, long_states, W_metab, b_metab);
    k_main<<<N_NODES, 128, SMEM_MAIN>>>(src, W_out, b_out, out);
}

// round 11
// speedup vs baseline: 1.6694x; 1.2051x over previous
#include <cuda_runtime.h>
#include <cuda_fp16.h>

#define N_NODES 2000
#define N_EDGES 16000
#define BB 4
#define L1D 12
#define IN_DIM 16
#define REF 32
#define HID 32
#define OUTD 16
#define NB (N_NODES*BB)   // 8000
#define MAXDEG 96

typedef unsigned long long u64;
typedef unsigned int u32;

// ---------------- scratch (device globals; no allocation) ----------------
__device__ __half g_sth[NB*384];     // fp16 state [nb][l*32+h]
__device__ __half g_A1h[NB*1024];    // A1 fp16 (bias incl)  -> pmb (P1)
__device__ __half g_A2h[NB*1024];    // A2 fp16 (bias incl)  -> k_main, [k][h]
__device__ __half g_B1h[NB*1024];    // B1 fp16              -> k_main, [k][h]
__device__ float  g_P1m[NB*384];     // P1 + mbs  (P4/mbd cancel in softmax -> never computed)
__device__ int    g_counts[N_NODES]; // zero at load; k_scan re-zeroes each replay
__device__ int    g_cursor[N_NODES];
__device__ int    g_offsets[N_NODES+1];
__device__ int    g_sorted[N_EDGES];

// ---------------- f32x2 packed helpers ----------------
__device__ __forceinline__ u64 pk2(float lo, float hi) {
    u64 r; asm("mov.b64 %0, {%1,%2};" : "=l"(r) : "f"(lo), "f"(hi)); return r;
}
__device__ __forceinline__ u64 pk2s(float v) { return pk2(v, v); }
__device__ __forceinline__ void upk2(float& lo, float& hi, u64 v) {
    asm("mov.b64 {%0,%1}, %2;" : "=f"(lo), "=f"(hi) : "l"(v));
}
__device__ __forceinline__ u64 fma2(u64 a, u64 b, u64 c) {
    u64 d; asm("fma.rn.f32x2 %0, %1, %2, %3;" : "=l"(d) : "l"(a), "l"(b), "l"(c)); return d;
}
__device__ __forceinline__ u64 add2(u64 a, u64 b) {
    u64 d; asm("add.rn.f32x2 %0, %1, %2;" : "=l"(d) : "l"(a), "l"(b)); return d;
}
__device__ __forceinline__ u32 h2u(u64 p) {
    float lo, hi; upk2(lo, hi, p);
    __half2 h = __floats2half2_rn(lo, hi);
    return *reinterpret_cast<u32*>(&h);
}

// ---------------- cp.async / ldmatrix / mma helpers ----------------
__device__ __forceinline__ void cpa16(u32 s, const void* g) {
    asm volatile("cp.async.cg.shared.global [%0], [%1], 16;" :: "r"(s), "l"(g));
}
__device__ __forceinline__ void cpcommit() { asm volatile("cp.async.commit_group;"); }
template<int N> __device__ __forceinline__ void cpwait() {
    asm volatile("cp.async.wait_group %0;" :: "n"(N));
}
__device__ __forceinline__ void ldsm4(u32& r0, u32& r1, u32& r2, u32& r3, u32 addr) {
    asm volatile("ldmatrix.sync.aligned.m8n8.x4.shared.b16 {%0,%1,%2,%3}, [%4];"
        : "=r"(r0), "=r"(r1), "=r"(r2), "=r"(r3) : "r"(addr));
}
__device__ __forceinline__ void ldsm4t(u32& r0, u32& r1, u32& r2, u32& r3, u32 addr) {
    asm volatile("ldmatrix.sync.aligned.m8n8.x4.trans.shared.b16 {%0,%1,%2,%3}, [%4];"
        : "=r"(r0), "=r"(r1), "=r"(r2), "=r"(r3) : "r"(addr));
}
__device__ __forceinline__ void mma16816(float& c0, float& c1, float& c2, float& c3,
                                         u32 a0, u32 a1, u32 a2, u32 a3, u32 b0, u32 b1) {
    asm volatile("mma.sync.aligned.m16n8k16.row.col.f32.f16.f16.f32 "
        "{%0,%1,%2,%3}, {%4,%5,%6,%7}, {%8,%9}, {%0,%1,%2,%3};"
        : "+f"(c0), "+f"(c1), "+f"(c2), "+f"(c3)
        : "r"(a0), "r"(a1), "r"(a2), "r"(a3), "r"(b0), "r"(b1));
}

// ---------------- L1: fused state(+hist) | meta GEMM ----------------
// grid 6000 x 128: blocks [0,2000) state+hist; [2000,6000) meta tiles
__global__ void __launch_bounds__(128) k_statehistmeta(
        const float* __restrict__ x, const float* __restrict__ W_in,
        const float* __restrict__ b_in, const int* __restrict__ dst,
        const float* __restrict__ mk, const float* __restrict__ W,
        const float* __restrict__ bW) {
    __shared__ __align__(16) float shm[9216];
    int t = threadIdx.x;
    int bx = blockIdx.x;

    if (bx < N_NODES) {
        int n = bx;
        float* xs = shm;
        float* ws = shm + 768;
        float* bs = shm + 1280;
        if (t < 8) atomicAdd(&g_counts[dst[8*n + t]], 1);
        for (int i = t; i < IN_DIM*HID; i += 128) ws[i] = W_in[i];
        if (t < HID) bs[t] = b_in[t];
        for (int i = t; i < BB*L1D*IN_DIM; i += 128) {
            int bl = i / IN_DIM, ii = i % IN_DIM;
            int b = bl / L1D, l = bl % L1D;
            xs[i] = x[((b*L1D + l)*N_NODES + n)*IN_DIM + ii];
        }
        __syncthreads();
        for (int o = t; o < BB*L1D*HID; o += 128) {
            int h = o % HID, bl = o / HID;
            float acc = bs[h];
            #pragma unroll
            for (int i = 0; i < IN_DIM; i++)
                acc = fmaf(xs[bl*IN_DIM + i], ws[i*HID + h], acc);
            g_sth[n*(BB*L1D*HID) + o] = __float2half_rn(acc);
        }
        return;
    }

    int m = bx - N_NODES;
    int nb0 = (m % 250) * 32;
    int c0  = (m / 250) * 128;
    bool needB = (c0 < 1024);       // B1 only needed for first half; B2 cancels in softmax
    float* mks = shm;
    float* wA  = shm + 1024;
    float* wB  = shm + 5120;
    for (int i = t; i < 1024; i += 128) {
        int row = i >> 5, r = i & 31;
        int nb = nb0 + row, n = nb >> 2, b = nb & 3;
        mks[i] = mk[(b*N_NODES + n)*REF + r];
    }
    for (int i = t; i < 1024; i += 128) {
        int r = (i*4) >> 7, c = (i*4) & 127;
        *(float4*)&wA[r*128 + c] = *(const float4*)&W[r*2048 + c0 + c];
        if (needB)
            *(float4*)&wB[r*128 + c] = *(const float4*)&W[(r + REF)*2048 + c0 + c];
    }
    __syncthreads();
    int tc = t & 15, tr = t >> 4;
    int row0 = tr * 4, col0 = tc * 8;
    u64 accA[4][4], accB[4][4];
    #pragma unroll
    for (int i = 0; i < 4; i++)
        #pragma unroll
        for (int j = 0; j < 4; j++) { accA[i][j] = 0ull; accB[i][j] = 0ull; }
    if (needB) {
        #pragma unroll 8
        for (int r = 0; r < REF; r++) {
            ulonglong2 wa0 = *(const ulonglong2*)&wA[r*128 + col0];
            ulonglong2 wa1 = *(const ulonglong2*)&wA[r*128 + col0 + 4];
            ulonglong2 wb0 = *(const ulonglong2*)&wB[r*128 + col0];
            ulonglong2 wb1 = *(const ulonglong2*)&wB[r*128 + col0 + 4];
            #pragma unroll
            for (int i = 0; i < 4; i++) {
                u64 a = pk2s(mks[(row0 + i)*32 + r]);
                accA[i][0] = fma2(a, wa0.x, accA[i][0]);
                accA[i][1] = fma2(a, wa0.y, accA[i][1]);
                accA[i][2] = fma2(a, wa1.x, accA[i][2]);
                accA[i][3] = fma2(a, wa1.y, accA[i][3]);
                accB[i][0] = fma2(a, wb0.x, accB[i][0]);
                accB[i][1] = fma2(a, wb0.y, accB[i][1]);
                accB[i][2] = fma2(a, wb1.x, accB[i][2]);
                accB[i][3] = fma2(a, wb1.y, accB[i][3]);
            }
        }
    } else {
        #pragma unroll 8
        for (int r = 0; r < REF; r++) {
            ulonglong2 wa0 = *(const ulonglong2*)&wA[r*128 + col0];
            ulonglong2 wa1 = *(const ulonglong2*)&wA[r*128 + col0 + 4];
            #pragma unroll
            for (int i = 0; i < 4; i++) {
                u64 a = pk2s(mks[(row0 + i)*32 + r]);
                accA[i][0] = fma2(a, wa0.x, accA[i][0]);
                accA[i][1] = fma2(a, wa0.y, accA[i][1]);
                accA[i][2] = fma2(a, wa1.x, accA[i][2]);
                accA[i][3] = fma2(a, wa1.y, accA[i][3]);
            }
        }
    }
    ulonglong2 bv0 = *(const ulonglong2*)&bW[c0 + col0];
    ulonglong2 bv1 = *(const ulonglong2*)&bW[c0 + col0 + 4];
    #pragma unroll
    for (int i = 0; i < 4; i++) {
        int nb = nb0 + row0 + i;
        u64 oa0 = add2(accA[i][0], bv0.x), oa1 = add2(accA[i][1], bv0.y);
        u64 oa2 = add2(accA[i][2], bv1.x), oa3 = add2(accA[i][3], bv1.y);
        uint4 ha = { h2u(oa0), h2u(oa1), h2u(oa2), h2u(oa3) };
        if (needB) {
            int off = nb*1024 + c0 + col0;
            *(uint4*)&g_A1h[off] = ha;
            uint4 hb = { h2u(accB[i][0]), h2u(accB[i][1]), h2u(accB[i][2]), h2u(accB[i][3]) };
            *(uint4*)&g_B1h[off] = hb;
        } else {
            int off = nb*1024 + (c0 - 1024) + col0;
            *(uint4*)&g_A2h[off] = ha;
        }
    }
}

// ---------------- L2: scan (re-zeroes g_counts for next replay) ----------------
__global__ void k_scan() {
    __shared__ int sb[1024];
    int t = threadIdx.x;
    int i0 = 2*t, i1 = 2*t + 1;
    int a0 = (i0 < N_NODES) ? g_counts[i0] : 0;
    int a1 = (i1 < N_NODES) ? g_counts[i1] : 0;
    sb[t] = a0 + a1;
    __syncthreads();
    for (int off = 1; off < 1024; off <<= 1) {
        int v = (t >= off) ? sb[t - off] : 0;
        __syncthreads();
        sb[t] += v;
        __syncthreads();
    }
    int excl = sb[t] - (a0 + a1);
    if (i0 < N_NODES) { g_offsets[i0] = excl;      g_cursor[i0] = excl;      g_counts[i0] = 0; }
    if (i1 < N_NODES) { g_offsets[i1] = excl + a0; g_cursor[i1] = excl + a0; g_counts[i1] = 0; }
    if (t == 1023) g_offsets[N_NODES] = sb[1023];
}

// ---------------- L3: fused pmb (P1m only) + scatter ----------------
__global__ void __launch_bounds__(128) k_pmbscatter(
        const int* __restrict__ dst,
        const float* __restrict__ mk, const float* __restrict__ Wmb,
        const float* __restrict__ bmb) {
    int nb = blockIdx.x, n = nb >> 2, b = nb & 3;
    int t = threadIdx.x;

    if (nb < 500 && t < 32) {
        int e = nb * 32 + t;
        if (e < N_EDGES) {
            int d = dst[e];
            int pos = atomicAdd(&g_cursor[d], 1);
            g_sorted[pos] = e;
        }
    }

    __shared__ float st[L1D*HID];
    __shared__ float A1[1024];
    __shared__ float mks[REF];
    __shared__ float mbsh[HID];
    // convert fp16 inputs to fp32 smem
    for (int i = t; i < 192; i += 128) {
        __half2 h = *((const __half2*)&g_sth[nb*384] + i);
        float2 f = __half22float2(h);
        st[2*i] = f.x; st[2*i + 1] = f.y;
    }
    for (int i = t; i < 512; i += 128) {
        __half2 h = *((const __half2*)&g_A1h[(size_t)nb*1024] + i);
        float2 f = __half22float2(h);
        A1[2*i] = f.x; A1[2*i + 1] = f.y;
    }
    if (t < REF) mks[t] = mk[(b*N_NODES + n)*REF + t];
    __syncthreads();
    if (t < HID) {
        float s1 = 0.f;
        #pragma unroll
        for (int r = 0; r < REF; r++)
            s1 = fmaf(mks[r], Wmb[r*HID + t], s1);
        mbsh[t] = s1;   // mbd cancels in softmax; never computed
    }
    __syncthreads();
    int h = t & 31, l0 = t >> 5;
    #pragma unroll
    for (int j = 0; j < 3; j++) {
        int l = l0 + 4*j;
        float p1 = 0.f;
        #pragma unroll
        for (int k = 0; k < HID; k++)
            p1 = fmaf(st[l*HID + k], A1[k*32 + h], p1);
        g_P1m[nb*384 + l*32 + h] = p1 + mbsh[h];
    }
}

// ---------------- L4: k_main — tensor-core edge attention (P4/mbd cancelled) ----------------
// per-warp smem bytes: B1s 2048 | dds 1024 | ssb 2x1024 | A2b 2x2048 | p1b 2x2048
#define PWB 13312
#define SMEM_MAIN (768 + 4*PWB)   // 54016 bytes -> 4 blocks/SM

__global__ void __launch_bounds__(128, 4) k_main(const int* __restrict__ src,
                                                 const float* __restrict__ W_out,
                                                 const float* __restrict__ b_out,
                                                 float* __restrict__ out) {
    extern __shared__ __align__(16) char sh[];
    int* ekeys = (int*)sh;              // 96
    int* slist = (int*)(sh + 384);      // 96

    int t = threadIdx.x, wid = t >> 5, lane = t & 31;
    int n = blockIdx.x, b = wid;
    int nbd = n*4 + b;
    int es = g_offsets[n];
    int deg = g_offsets[n+1] - es;
    int degc = (deg < MAXDEG) ? deg : MAXDEG;

    if (t < degc) ekeys[t] = g_sorted[es + t];

    char* wb = sh + 768 + wid*PWB;
    __half* B1s = (__half*)wb;                 // [k][h] 32x32
    __half* dds = (__half*)(wb + 2048);        // [l][k] 16x32 (rows 12-15 zero)
    __half* ssb = (__half*)(wb + 3072);        // 2 x [l][k] 16x32
    __half* A2b = (__half*)(wb + 5120);        // 2 x [k][h] 32x32
    float*  p1b = (float*)(wb + 9216);         // 2 x [l][h] 16x32 (rows 12-15 zero)
    float*  news = (float*)(wb + 5120);        // alias over A2b after loop

    // prologue copies (per warp)
    {
        const uint4* pb1 = (const uint4*)&g_B1h[(size_t)nbd*1024];
        #pragma unroll
        for (int i = lane; i < 128; i += 32) ((uint4*)B1s)[i] = pb1[i];
        const uint4* pdd = (const uint4*)&g_sth[(size_t)nbd*384];
        if (lane < 32) ((uint4*)dds)[lane] = pdd[lane];
        if (lane < 16) ((uint4*)dds)[32 + lane] = pdd[32 + lane];
        uint4 z = {0,0,0,0};
        if (lane < 16) ((uint4*)dds)[48 + lane] = z;
        #pragma unroll
        for (int v = 0; v < 2; v++) {
            if (lane < 16) ((uint4*)(ssb + v*512))[48 + lane] = z;
            if (lane < 32) { ((float4*)(p1b + v*512))[96 + lane] = make_float4(0,0,0,0); }
        }
    }
    __syncthreads();

    if (t < degc) {
        int key = ekeys[t], r = 0;
        for (int j = 0; j < degc; j++) r += (ekeys[j] < key);
        slist[r] = src[key];
    }
    __syncthreads();

    // fragment-lane geometry
    int qr = lane & 7, q = lane >> 3;
    u32 offM = (u32)((qr + (q & 1)*8)*64 + (q >> 1)*16);
    int r0 = lane >> 2;
    int cbase = 2*(lane & 3);

    u32 sB1 = (u32)__cvta_generic_to_shared(B1s);
    u32 sDD = (u32)__cvta_generic_to_shared(dds);
    u32 sSS = (u32)__cvta_generic_to_shared(ssb);
    u32 sA2 = (u32)__cvta_generic_to_shared(A2b);
    u32 sP1 = (u32)__cvta_generic_to_shared(p1b);

    // fixed fragments: B1 (8 frags), dd (2 tiles)
    u32 b1f[2][4][2];
    #pragma unroll
    for (int s = 0; s < 2; s++)
        #pragma unroll
        for (int p = 0; p < 2; p++) {
            u32 r0_, r1_, r2_, r3_;
            ldsm4t(r0_, r1_, r2_, r3_, sB1 + offM + s*1024 + p*32);
            b1f[s][p*2][0] = r0_;   b1f[s][p*2][1] = r1_;
            b1f[s][p*2+1][0] = r2_; b1f[s][p*2+1][1] = r3_;
        }
    u32 ddf[2][4];
    #pragma unroll
    for (int s = 0; s < 2; s++)
        ldsm4(ddf[s][0], ddf[s][1], ddf[s][2], ddf[s][3], sDD + offM + s*32);

    float den[4][4], num[4][4];
    #pragma unroll
    for (int j = 0; j < 4; j++)
        #pragma unroll
        for (int i = 0; i < 4; i++) { den[j][i] = 0.f; num[j][i] = 0.f; }

    auto stageEdge = [&](int nbs, int v) {
        const char* pa = (const char*)&g_A2h[(size_t)nbs*1024];
        u32 da = sA2 + v*2048;
        #pragma unroll
        for (int r = 0; r < 4; r++) {
            int c = lane + 32*r;
            cpa16(da + c*16, pa + c*16);
        }
        const char* ps = (const char*)&g_sth[(size_t)nbs*384];
        u32 dsa = sSS + v*1024;
        cpa16(dsa + lane*16, ps + lane*16);
        if (lane < 16) cpa16(dsa + (32+lane)*16, ps + (32+lane)*16);
        const char* pp = (const char*)&g_P1m[(size_t)nbs*384];
        u32 dp = sP1 + v*2048;
        #pragma unroll
        for (int r = 0; r < 3; r++) {
            int c = lane + 32*r;
            cpa16(dp + c*16, pp + c*16);
        }
    };

    auto computeEdge = [&](int v) {
        __half* ssv = ssb + v*512;
        float*  p1v = p1b + v*512;
        u32 ssbase = sSS + v*1024;
        u32 a2base = sA2 + v*2048;
        u32 ssf[2][4];
        #pragma unroll
        for (int s = 0; s < 2; s++)
            ldsm4(ssf[s][0], ssf[s][1], ssf[s][2], ssf[s][3], ssbase + offM + s*32);
        u32 a2f[2][4][2];
        #pragma unroll
        for (int s = 0; s < 2; s++)
            #pragma unroll
            for (int p = 0; p < 2; p++) {
                u32 r0_, r1_, r2_, r3_;
                ldsm4t(r0_, r1_, r2_, r3_, a2base + offM + s*1024 + p*32);
                a2f[s][p*2][0] = r0_;   a2f[s][p*2][1] = r1_;
                a2f[s][p*2+1][0] = r2_; a2f[s][p*2+1][1] = r3_;
            }
        #pragma unroll
        for (int j = 0; j < 4; j++) {
            float c0 = 0.f, c1 = 0.f, c2 = 0.f, c3 = 0.f;
            mma16816(c0, c1, c2, c3, ssf[0][0], ssf[0][1], ssf[0][2], ssf[0][3],
                     b1f[0][j][0], b1f[0][j][1]);
            mma16816(c0, c1, c2, c3, ssf[1][0], ssf[1][1], ssf[1][2], ssf[1][3],
                     b1f[1][j][0], b1f[1][j][1]);
            mma16816(c0, c1, c2, c3, ddf[0][0], ddf[0][1], ddf[0][2], ddf[0][3],
                     a2f[0][j][0], a2f[0][j][1]);
            mma16816(c0, c1, c2, c3, ddf[1][0], ddf[1][1], ddf[1][2], ddf[1][3],
                     a2f[1][j][0], a2f[1][j][1]);
            int col = 8*j + cbase;
            float2 plo = *(const float2*)&p1v[r0*32 + col];
            float2 phi = *(const float2*)&p1v[(r0+8)*32 + col];   // rows 12-15 zeroed
            float a0 = c0 + plo.x;
            float a1 = c1 + plo.y;
            float a2_ = c2 + phi.x;
            float a3 = c3 + phi.y;
            float w0 = __expf(a0), w1 = __expf(a1), w2 = __expf(a2_), w3 = __expf(a3);
            den[j][0] += w0; den[j][1] += w1; den[j][2] += w2; den[j][3] += w3;
            __half2 hlo = *(const __half2*)&ssv[r0*32 + col];
            __half2 hhi = *(const __half2*)&ssv[(r0+8)*32 + col];  // rows 12-15 zero
            float2 flo = __half22float2(hlo), fhi = __half22float2(hhi);
            num[j][0] = fmaf(w0, flo.x, num[j][0]);
            num[j][1] = fmaf(w1, flo.y, num[j][1]);
            num[j][2] = fmaf(w2, fhi.x, num[j][2]);
            num[j][3] = fmaf(w3, fhi.y, num[j][3]);
        }
    };

    for (int m = 0; m < degc + 1; m++) {
        if (m < degc) {
            stageEdge(slist[m]*4 + b, m & 1);
            cpcommit();
        }
        if (m > 0) {
            if (m < degc) cpwait<1>(); else cpwait<0>();
            __syncwarp();
            computeEdge((m - 1) & 1);
            __syncwarp();
        }
    }

    // overflow fallback (deg > MAXDEG): synchronous, rare
    for (int i = MAXDEG; i < deg; i++) {
        int nbs = src[g_sorted[es + i]]*4 + b;
        stageEdge(nbs, 0);
        cpcommit();
        cpwait<0>();
        __syncwarp();
        computeEdge(0);
        __syncwarp();
    }
    __syncwarp();

    // finalize softmax into news (aliases A2b; staging is dead now)
    #pragma unroll
    for (int j = 0; j < 4; j++) {
        int col = 8*j + cbase;
        float d0 = den[j][0], d1 = den[j][1], d2 = den[j][2], d3 = den[j][3];
        float2 lo;
        lo.x = __fdividef(num[j][0], d0 == 0.f ? 1.f : d0);
        lo.y = __fdividef(num[j][1], d1 == 0.f ? 1.f : d1);
        *(float2*)&news[r0*32 + col] = lo;
        if (r0 < 4) {
            float2 hi;
            hi.x = __fdividef(num[j][2], d2 == 0.f ? 1.f : d2);
            hi.y = __fdividef(num[j][3], d3 == 0.f ? 1.f : d3);
            *(float2*)&news[(r0+8)*32 + col] = hi;
        }
    }
    __syncwarp();

    // output projection
    for (int oi = lane; oi < L1D*OUTD; oi += 32) {
        int l = oi >> 4, o = oi & 15;
        float acc = __ldg(&b_out[o]);
        #pragma unroll
        for (int h = 0; h < HID; h++)
            acc = fmaf(news[l*32 + h], __ldg(&W_out[h*16 + o]), acc);
        out[((b*L1D + l)*N_NODES + n)*OUTD + o] = acc;
    }
}

// ---------------- launch ----------------
extern "C" void kernel_launch(void* const* d_in, const int* in_sizes, int n_in,
                              void* d_out, int out_size) {
    const float* long_states = (const float*)d_in[0];
    const float* short_in    = (const float*)d_in[1];
    const int*   src         = (const int*)d_in[2];
    const int*   dst         = (const int*)d_in[3];
    const float* W_in        = (const float*)d_in[4];
    const float* b_in        = (const float*)d_in[5];
    const float* W_metaW     = (const float*)d_in[6];
    const float* b_metaW     = (const float*)d_in[7];
    const float* W_metab     = (const float*)d_in[8];
    const float* b_metab     = (const float*)d_in[9];
    const float* W_out       = (const float*)d_in[10];
    const float* b_out       = (const float*)d_in[11];
    float* out = (float*)d_out;

    cudaFuncSetAttribute(k_main, cudaFuncAttributeMaxDynamicSharedMemorySize, SMEM_MAIN);

    k_statehistmeta<<<N_NODES + 4000, 128>>>(short_in, W_in, b_in, dst,
                                             long_states, W_metaW, b_metaW);
    k_scan<<<1, 1024>>>();
    k_pmbscatter<<<NB, 128>>>(dst, long_states, W_metab, b_metab);
    k_main<<<N_NODES, 128, SMEM_MAIN>>>(src, W_out, b_out, out);
}